// round 1
// baseline (speedup 1.0000x reference)
#include <cuda_runtime.h>
#include <cuda_bf16.h>

// dense_image_warp: out[b,y,x,c] = bilinear(image, (y,x) - flow[b,y,x])
// B=8, H=256, W=256, C=64 (fp32). One thread per float4 (4 channels).
// 16 threads per pixel; channel-contiguous layout => coalesced gathers/stores.

__global__ __launch_bounds__(256) void warp_kernel(
    const float4* __restrict__ img,    // [B,H,W,C] as float4, pixel stride 16
    const float2* __restrict__ flow,   // [B,H,W,2] as float2, one per pixel
    float4* __restrict__ out)
{
    const int tid = blockIdx.x * blockDim.x + threadIdx.x;
    const int c4 = tid & 15;          // channel group 0..15
    const int p  = tid >> 4;          // pixel index: b*65536 + y*256 + x
    const int x  = p & 255;
    const int y  = (p >> 8) & 255;
    const int b  = p >> 16;

    const float2 f = __ldg(&flow[p]);
    const float qy = (float)y - f.x;
    const float qx = (float)x - f.y;

    float fy = floorf(qy); fy = fminf(fmaxf(fy, 0.0f), 254.0f);
    float fx = floorf(qx); fx = fminf(fmaxf(fx, 0.0f), 254.0f);
    const float ay = fminf(fmaxf(qy - fy, 0.0f), 1.0f);
    const float ax = fminf(fmaxf(qx - fx, 0.0f), 1.0f);

    const int iy = (int)fy;
    const int ix = (int)fx;

    // base in float4 units: (((b*256 + iy)*256 + ix) * 64 + c4*4) / 4
    const long base = (((long)((b << 8) + iy) << 8) + ix) * 16 + c4;
    const float4 tl = __ldg(img + base);
    const float4 tr = __ldg(img + base + 16);          // x+1
    const float4 bl = __ldg(img + base + 16 * 256);    // y+1
    const float4 br = __ldg(img + base + 16 * 256 + 16);

    float4 r;
    {
        float top, bot;
        top = fmaf(ax, tr.x - tl.x, tl.x);
        bot = fmaf(ax, br.x - bl.x, bl.x);
        r.x = fmaf(ay, bot - top, top);
        top = fmaf(ax, tr.y - tl.y, tl.y);
        bot = fmaf(ax, br.y - bl.y, bl.y);
        r.y = fmaf(ay, bot - top, top);
        top = fmaf(ax, tr.z - tl.z, tl.z);
        bot = fmaf(ax, br.z - bl.z, bl.z);
        r.z = fmaf(ay, bot - top, top);
        top = fmaf(ax, tr.w - tl.w, tl.w);
        bot = fmaf(ax, br.w - bl.w, bl.w);
        r.w = fmaf(ay, bot - top, top);
    }
    out[tid] = r;
}

extern "C" void kernel_launch(void* const* d_in, const int* in_sizes, int n_in,
                              void* d_out, int out_size)
{
    const float4* img  = (const float4*)d_in[0];
    const float2* flow = (const float2*)d_in[1];
    float4* out = (float4*)d_out;

    // out_size = 8*256*256*64 = 33554432 floats -> 8388608 float4 threads
    const int threads = out_size / 4;
    const int block = 256;
    const int grid = (threads + block - 1) / block;  // 32768
    warp_kernel<<<grid, block>>>(img, flow, out);
}